// round 4
// baseline (speedup 1.0000x reference)
#include <cuda_runtime.h>
#include <cstdint>
#include <math.h>

#define CS     8
#define NG     192
#define NGP    194
#define TSTEPS 256
#define NTHR   384
#define NBLK   (TSTEPS / 2)

__device__ __forceinline__ uint32_t s2u(const void* p) {
    return (uint32_t)__cvta_generic_to_shared((void*)p);
}
__device__ __forceinline__ uint32_t mapa_u32(uint32_t a, uint32_t r) {
    uint32_t d;
    asm("mapa.shared::cluster.u32 %0, %1, %2;" : "=r"(d) : "r"(a), "r"(r));
    return d;
}
__device__ __forceinline__ void st_cluster_f32(uint32_t a, float v) {
    asm volatile("st.shared::cluster.f32 [%0], %1;" :: "r"(a), "f"(v) : "memory");
}
__device__ __forceinline__ void cl_arrive() {
    asm volatile("barrier.cluster.arrive.aligned;" ::: "memory");
}
__device__ __forceinline__ void cl_wait() {
    asm volatile("barrier.cluster.wait.aligned;" ::: "memory");
}

__device__ __forceinline__ float pml1(int i) {
    int d;
    if (i <= 20)           d = 20 - i;
    else if (i >= NG - 21) d = i - (NG - 21);
    else return 0.0f;
    double t = (double)d * 0.05;
    double t2 = t * t;
    return (float)(3.0 * t2 * t2);
}

__global__ void __cluster_dims__(CS, 1, 1) __launch_bounds__(NTHR, 1)
wave_kernel(const float* __restrict__ x, const float* __restrict__ rho,
            float* __restrict__ out)
{
    // halo[blockParity][side 0=top/1=bot][0:y(t)±2, 1:y(t)±1, 2:y(t-1)±1][col+1]
    __shared__ float halo[2][2][3][NGP];
    __shared__ float rb[2][2][NG];        // [0=end,1=mid][0=row11,1=row12][col]
    __shared__ float bufL[2][2][7][12];   // [set][rgrp][cw guard][ownrow]
    __shared__ float bufR[2][2][7][12];
    __shared__ float xs[TSTEPS];
    __shared__ float pbuf[3];

    const int tid  = threadIdx.x;
    const int col  = tid % NG;
    const int rgrp = tid / NG;            // 0: rows 0-11 (+ext -1), 1: rows 12-23 (+ext 24)
    const int lane = tid & 31;
    const int cw   = col >> 5;
    const int rank = blockIdx.x % CS;
    const int batch= blockIdx.x / CS;

    for (int i = tid; i < 2*2*3*NGP; i += NTHR) (&halo[0][0][0][0])[i] = 0.f;
    for (int i = tid; i < 2*2*NG;    i += NTHR) (&rb[0][0][0])[i] = 0.f;
    for (int i = tid; i < 2*2*7*12;  i += NTHR) { (&bufL[0][0][0][0])[i] = 0.f; (&bufR[0][0][0][0])[i] = 0.f; }
    for (int i = tid; i < TSTEPS;    i += NTHR) xs[i] = x[batch * TSTEPS + i];

    // ---- coefficients for 13 rows (12 owned + 1 extended) ----
    const int gbase = rank * 24 + (rgrp ? 12 : -1);   // global row of idx 0
    const float HM2 = (float)(1.0 / (2.01 * 2.01));
    float Qp[13], Qm[13], Rc[13], cur[13], prev[13];
#pragma unroll
    for (int i = 0; i < 13; ++i) {
        int g  = gbase + i;
        int gc = min(max(g, 0), NG - 1);
        float cc = rho[gc * NG + col];
        float nn = (gc > 0)      ? rho[(gc - 1) * NG + col] : 0.f;
        float ss = (gc < NG - 1) ? rho[(gc + 1) * NG + col] : 0.f;
        float ww = (col > 0)     ? rho[gc * NG + col - 1]   : 0.f;
        float ee = (col < NG-1)  ? rho[gc * NG + col + 1]   : 0.f;
        float lpf = 0.5f * cc + 0.125f * (nn + ss + ww + ee);
        float pr  = (1.0f + tanhf(100.0f * (lpf - 0.5f))) * 0.5f;
        float c   = 1.0f - 0.1f * pr;
        float bx = pml1(gc), by = pml1(col);
        float bb = sqrtf(bx * bx + by * by);
        float A1 = 1.0f / (1.0f + 0.5f * bb);
        float Q  = A1 * (1.0f - 0.5f * bb);
        float R  = A1 * (c * c) * HM2;
        Qp[i] = 1.0f + Q - 4.0f * R; Qm[i] = Q; Rc[i] = R;
        cur[i] = 0.f; prev[i] = 0.f;
    }

    const bool isL = (lane == 0), isR = (lane == 31), isEdge = isL | isR;
    const int  side = rgrp;               // my extended side: rgrp0=top, rgrp1=bottom
    const bool hasExt = rgrp == 0 ? (rank > 0) : (rank < CS - 1);

    const float* hA[2]; const float* hB[2]; const float* hC[2]; const float* hEg[2];
#pragma unroll
    for (int p = 0; p < 2; ++p) {
        hA[p]  = &halo[p][side][0][col + 1];
        hB[p]  = &halo[p][side][1][col + 1];
        hC[p]  = &halo[p][side][2][col + 1];
        hEg[p] = &halo[p][side][1][col + 1 + (isL ? -1 : 1)];
    }
    uint32_t pA[2], pB[2], pC[2];
    {
        int nr = rgrp == 0 ? max(rank - 1, 0) : min(rank + 1, CS - 1);
        int ts = 1 - rgrp;                 // target side in neighbor
#pragma unroll
        for (int p = 0; p < 2; ++p) {
            pA[p] = mapa_u32(s2u(&halo[p][ts][0][col + 1]), (uint32_t)nr);
            pB[p] = mapa_u32(s2u(&halo[p][ts][1][col + 1]), (uint32_t)nr);
            pC[p] = mapa_u32(s2u(&halo[p][ts][2][col + 1]), (uint32_t)nr);
        }
    }
    // colbuf pointers pre-shifted so they index by stencil idx i (owned rows)
    const int adj = (rgrp == 0) ? 1 : 0;
    const float* eR0 = (isL ? &bufR[0][rgrp][cw][0] : &bufL[0][rgrp][cw + 1][0]) - adj;
    const float* eR1 = (isL ? &bufR[1][rgrp][cw][0] : &bufL[1][rgrp][cw + 1][0]) - adj;
    float*       eW0 = (isL ? &bufL[0][rgrp][cw][0] : &bufR[0][rgrp][cw + 1][0]) - adj;
    float*       eW1 = (isL ? &bufL[1][rgrp][cw][0] : &bufR[1][rgrp][cw + 1][0]) - adj;

    // Source (40,96): rank1 rgrp1 i=4. Probes (160,{48,96,144}): rank6 rgrp1 i=4.
    const bool isSrc = (rank == 1) && (rgrp == 1) && (col == 96);
    const bool isPrb = (rank == 6) && (rgrp == 1) &&
                       ((col == 48) | (col == 96) | (col == 144));
    float pacc = 0.f;

    cl_arrive(); cl_wait();    // init visible cluster-wide

    for (int b = 0; b < NBLK; ++b) {
        const int p  = b & 1;
        const int np = p ^ 1;
        const float xs1 = xs[2 * b];
        const float xs2 = xs[2 * b + 1];

        // ---- block-start boundary loads ----
        float yNv, ySv;
        if (rgrp == 0) {
            cur[0]  = *hB[p];  prev[0] = *hC[p];
            yNv = *hA[p];      ySv = rb[0][1][col];
        } else {
            cur[12] = *hB[p];  prev[12] = *hC[p];
            ySv = *hA[p];      yNv = rb[0][0][col];
        }

        // ---- step 1: t -> t+1 on 13 rows (result into prev[]) ----
#pragma unroll
        for (int i = 0; i < 13; ++i) {
            float c = cur[i];
            float w = __shfl_up_sync(0xffffffffu, c, 1);
            float e = __shfl_down_sync(0xffffffffu, c, 1);
            if (isEdge) {
                float pv;
                if ((i == 0 && rgrp == 0) || (i == 12 && rgrp == 1)) pv = *hEg[p];
                else pv = eR0[i];
                if (isL) w = pv; else e = pv;
            }
            float nn = (i == 0)  ? yNv : cur[i - 1];
            float ss = (i == 12) ? ySv : cur[i + 1];
            float yn = fmaf(Qp[i], c, fmaf(-Qm[i], prev[i], Rc[i] * ((nn + ss) + (w + e))));
            if (i == 4) {
                if (isSrc) yn += xs1;
                if (isPrb) pacc = fmaf(yn, yn, pacc);
            }
            prev[i] = yn;
            if (isEdge) {
                if (!((i == 0 && rgrp == 0) || (i == 12 && rgrp == 1))) eW1[i] = yn;
            }
        }
        if (rgrp == 0) {
            if (!hasExt) prev[0] = 0.f;
            rb[1][0][col] = prev[12];      // y(t+1) row 11
        } else {
            if (!hasExt) prev[12] = 0.f;
            rb[1][1][col] = prev[0];       // y(t+1) row 12
        }
        __syncthreads();                    // mid-block: t+1 boundary data visible

        const float yNm = (rgrp == 1) ? rb[1][0][col] : 0.f;  // y(t+1) row 11
        const float ySm = (rgrp == 0) ? rb[1][1][col] : 0.f;  // y(t+1) row 12

        // ---- step 2: t+1 -> t+2 on owned rows (result into cur[]) ----
        auto s2 = [&](int i) {
            float c = prev[i];
            float w = __shfl_up_sync(0xffffffffu, c, 1);
            float e = __shfl_down_sync(0xffffffffu, c, 1);
            if (isEdge) { float pv = eR1[i]; if (isL) w = pv; else e = pv; }
            float nn = (rgrp == 1 && i == 0)  ? yNm : prev[i - 1];
            float ss = (rgrp == 0 && i == 12) ? ySm : prev[i + 1];
            float yn = fmaf(Qp[i], c, fmaf(-Qm[i], cur[i], Rc[i] * ((nn + ss) + (w + e))));
            if (i == 4) {
                if (isSrc) yn += xs2;
                if (isPrb) pacc = fmaf(yn, yn, pacc);
            }
            cur[i] = yn;
            if (isEdge) eW0[i] = yn;
        };

        // boundary-critical rows first, then push, then arrive
        if (rgrp == 0) {
            s2(1); s2(2);
            if (hasExt) {
                st_cluster_f32(pB[np], cur[1]);   // y(t+2) row 0
                st_cluster_f32(pA[np], cur[2]);   // y(t+2) row 1
                st_cluster_f32(pC[np], prev[1]);  // y(t+1) row 0
            }
        } else {
            s2(11); s2(10);
            if (hasExt) {
                st_cluster_f32(pB[np], cur[11]);  // y(t+2) row 23
                st_cluster_f32(pA[np], cur[10]);  // y(t+2) row 22
                st_cluster_f32(pC[np], prev[11]); // y(t+1) row 23
            }
        }
        cl_arrive();

        if (rgrp == 0) {
#pragma unroll
            for (int i = 3; i <= 12; ++i) s2(i);
            rb[0][0][col] = cur[12];      // y(t+2) row 11
        } else {
#pragma unroll
            for (int i = 0; i <= 9; ++i) s2(i);
            rb[0][1][col] = cur[0];       // y(t+2) row 12
        }
        __syncthreads();
        cl_wait();
    }

    if (isPrb) pbuf[(col - 48) / 48] = pacc;
    __syncthreads();
    if (rank == 6 && tid == 0) {
        float a = pbuf[0], b2 = pbuf[1], c = pbuf[2];
        float s = a + b2 + c;
        out[batch * 3 + 0] = a / s;
        out[batch * 3 + 1] = b2 / s;
        out[batch * 3 + 2] = c / s;
    }
}

extern "C" void kernel_launch(void* const* d_in, const int* in_sizes, int n_in,
                              void* d_out, int out_size)
{
    (void)in_sizes; (void)n_in; (void)out_size;
    const float* x   = (const float*)d_in[0];   // (4,256) f32
    const float* rho = (const float*)d_in[1];   // (192,192) f32
    float* out = (float*)d_out;                 // (4,3) f32
    wave_kernel<<<dim3(CS * 4), dim3(NTHR)>>>(x, rho, out);
}

// round 5
// speedup vs baseline: 1.6101x; 1.6101x over previous
#include <cuda_runtime.h>
#include <cstdint>
#include <math.h>

#define CS     8      // CTAs per batch (row slabs)
#define ROWS   24     // rows per CTA
#define PITCH  196    // 2 zero cols + 192 data + 2 zero cols
#define LROWS  26     // ROWS + 2 halo rows
#define NG     192
#define TSTEPS 256
#define NTHR   768
#define KPT    6      // rows per thread (4 row-groups of 192 threads)

__device__ __forceinline__ uint32_t s2u(const void* p) {
    return (uint32_t)__cvta_generic_to_shared((void*)p);
}
__device__ __forceinline__ uint32_t mapa_u32(uint32_t a, uint32_t r) {
    uint32_t d;
    asm("mapa.shared::cluster.u32 %0, %1, %2;" : "=r"(d) : "r"(a), "r"(r));
    return d;
}
__device__ __forceinline__ void st_cluster_f32(uint32_t a, float v) {
    asm volatile("st.shared::cluster.f32 [%0], %1;" :: "r"(a), "f"(v) : "memory");
}
__device__ __forceinline__ void cl_arrive() {
    asm volatile("barrier.cluster.arrive.aligned;" ::: "memory");
}
__device__ __forceinline__ void cl_wait() {
    asm volatile("barrier.cluster.wait.aligned;" ::: "memory");
}

// PML 1D profile: v[k] = 3*(k/20)^4
__device__ __forceinline__ float pml1(int i) {
    int d;
    if (i <= 20)           d = 20 - i;
    else if (i >= NG - 21) d = i - (NG - 21);
    else return 0.0f;
    double t = (double)d * 0.05;
    double t2 = t * t;
    return (float)(3.0 * t2 * t2);
}

__global__ void __cluster_dims__(CS, 1, 1) __launch_bounds__(NTHR, 1)
wave_kernel(const float* __restrict__ x, const float* __restrict__ rho,
            float* __restrict__ out)
{
    __shared__ float bufs[2][LROWS * PITCH];  // double-buffered y field
    __shared__ float xs[TSTEPS];
    __shared__ float pbuf[3];

    const int tid   = threadIdx.x;
    const int col   = tid % NG;       // 0..191
    const int rgrp  = tid / NG;       // 0..3 (rows 6*rgrp .. 6*rgrp+5)
    const int rank  = blockIdx.x % CS;
    const int batch = blockIdx.x / CS;

    for (int i = tid; i < 2 * LROWS * PITCH; i += NTHR) (&bufs[0][0])[i] = 0.f;
    for (int i = tid; i < TSTEPS; i += NTHR) xs[i] = x[batch * TSTEPS + i];

    // ---- Per-cell coefficients: yn = Qp*c - Qm*y2 + Rc*(n+s+w+e) ----
    const float HM2 = (float)(1.0 / (2.01 * 2.01));
    float Qp[KPT], Qm[KPT], Rc[KPT], y2[KPT];
#pragma unroll
    for (int k = 0; k < KPT; ++k) {
        const int g = rank * ROWS + rgrp * KPT + k;
        float cc = rho[g * NG + col];
        float nn = (g > 0)      ? rho[(g - 1) * NG + col] : 0.f;
        float ss = (g < NG - 1) ? rho[(g + 1) * NG + col] : 0.f;
        float ww = (col > 0)    ? rho[g * NG + col - 1]   : 0.f;
        float ee = (col < NG-1) ? rho[g * NG + col + 1]   : 0.f;
        float lpf = 0.5f * cc + 0.125f * (nn + ss + ww + ee);
        float pr  = (1.0f + tanhf(100.0f * (lpf - 0.5f))) * 0.5f;
        float c   = 1.0f - 0.1f * pr;
        float bx = pml1(g), by = pml1(col);
        float bb = sqrtf(bx * bx + by * by);
        float A1 = 1.0f / (1.0f + 0.5f * bb);
        float Q  = A1 * (1.0f - 0.5f * bb);
        float R  = A1 * (c * c) * HM2;
        Qp[k] = 1.0f + Q - 4.0f * R;   // coefficient on center
        Qm[k] = Q;                     // coefficient on y2
        Rc[k] = R;                     // coefficient on 4-neighbor sum
        y2[k] = 0.f;
    }

    const int base = rgrp * KPT + 1;   // first local data row in buffer coords
    const float* p0 = &bufs[0][base * PITCH + col + 2];
    const float* p1 = &bufs[1][base * PITCH + col + 2];

    // Halo-push (boundary threads only): rgrp0 pushes row0 up, rgrp3 pushes row23 down.
    const bool doUp = (rank > 0)      && (rgrp == 0);
    const bool doDn = (rank < CS - 1) && (rgrp == 3);
    uint32_t upA[2] = {0, 0}, dnA[2] = {0, 0};
    if (doUp) {
        upA[0] = mapa_u32(s2u(&bufs[0][(ROWS + 1) * PITCH + col + 2]), (uint32_t)(rank - 1));
        upA[1] = mapa_u32(s2u(&bufs[1][(ROWS + 1) * PITCH + col + 2]), (uint32_t)(rank - 1));
    }
    if (doDn) {
        dnA[0] = mapa_u32(s2u(&bufs[0][col + 2]), (uint32_t)(rank + 1));
        dnA[1] = mapa_u32(s2u(&bufs[1][col + 2]), (uint32_t)(rank + 1));
    }

    // Source (40,96): rank1, local row 16 -> rgrp2, k=4. Probes (160,{48,96,144}): rank6, rgrp2, k=4.
    const bool isSrc = (rank == 1) && (rgrp == 2) && (col == 96);
    const bool isPrb = (rank == 6) && (rgrp == 2) &&
                       ((col == 48) | (col == 96) | (col == 144));
    float pacc = 0.f;

    cl_arrive(); cl_wait();   // zeros + setup visible cluster-wide

    for (int t = 0; t < TSTEPS; ++t) {
        const int wb = (t & 1) ^ 1;
        const float* rp = (t & 1) ? p1 : p0;
        float* wp = const_cast<float*>((t & 1) ? p0 : p1);

        // ---- phase A: CTA-boundary rows + halo push + arrive ----
        if (rgrp == 0) {
            float c  = rp[0];
            float n  = rp[-PITCH];         // halo row (pushed by neighbor last step)
            float s  = rp[PITCH];
            float wv = rp[-1];
            float ev = rp[1];
            float yn = fmaf(Qp[0], c, fmaf(-Qm[0], y2[0], Rc[0] * ((n + s) + (wv + ev))));
            y2[0] = c;
            wp[0] = yn;
            if (doUp) st_cluster_f32(upA[wb], yn);
        } else if (rgrp == 3) {
            const int k = KPT - 1;
            float c  = rp[k * PITCH];
            float n  = rp[(k - 1) * PITCH];
            float s  = rp[(k + 1) * PITCH];  // halo row
            float wv = rp[k * PITCH - 1];
            float ev = rp[k * PITCH + 1];
            float yn = fmaf(Qp[k], c, fmaf(-Qm[k], y2[k], Rc[k] * ((n + s) + (wv + ev))));
            y2[k] = c;
            wp[k * PITCH] = yn;
            if (doDn) st_cluster_f32(dnA[wb], yn);
        }
        cl_arrive();   // release halo push; interior compute overlaps barrier propagation

        // ---- phase B: remaining rows ----
        const int kLo = (rgrp == 0) ? 1 : 0;
        const int kHi = (rgrp == 3) ? KPT - 1 : KPT;
        {
            float n = rp[(kLo - 1) * PITCH];
            float c = rp[kLo * PITCH];
#pragma unroll
            for (int k = 0; k < KPT; ++k) {
                if (k < kLo || k >= kHi) continue;   // unrolled; predicates fold per rgrp
                float s  = rp[(k + 1) * PITCH];
                float wv = rp[k * PITCH - 1];
                float ev = rp[k * PITCH + 1];
                float yn = fmaf(Qp[k], c, fmaf(-Qm[k], y2[k], Rc[k] * ((n + s) + (wv + ev))));
                if (k == 4) {
                    if (isSrc) yn += xs[t];
                    if (isPrb) pacc = fmaf(yn, yn, pacc);
                }
                wp[k * PITCH] = yn;
                y2[k] = c;
                n = c;
                c = s;
            }
        }
        __syncthreads();   // interior writes visible intra-CTA (arrive was early)
        cl_wait();         // neighbors' halo pushes visible
    }

    if (isPrb) pbuf[(col - 48) / 48] = pacc;
    __syncthreads();
    if (rank == 6 && tid == 0) {
        float a = pbuf[0], b = pbuf[1], cc = pbuf[2];
        float sum = a + b + cc;
        out[batch * 3 + 0] = a / sum;
        out[batch * 3 + 1] = b / sum;
        out[batch * 3 + 2] = cc / sum;
    }
}

extern "C" void kernel_launch(void* const* d_in, const int* in_sizes, int n_in,
                              void* d_out, int out_size)
{
    (void)in_sizes; (void)n_in; (void)out_size;
    const float* x   = (const float*)d_in[0];   // (4,256) f32
    const float* rho = (const float*)d_in[1];   // (192,192) f32
    float* out = (float*)d_out;                 // (4,3) f32
    wave_kernel<<<dim3(CS * 4), dim3(NTHR)>>>(x, rho, out);
}

// round 6
// speedup vs baseline: 1.7247x; 1.0712x over previous
#include <cuda_runtime.h>
#include <cstdint>
#include <math.h>

#define CS     8
#define NG     192
#define NGP    194
#define PITCH  196
#define BROWS  26                 // buffer rows = field rows -1..24
#define NTHR   768
#define TSTEPS 256
#define NBLK   (TSTEPS / 2)
#define BUFSZ  (BROWS * PITCH)
#define HALOSZ (2 * 2 * 3 * NGP)  // [blockparity][side][idx][col+1]
#define SMEMFLOATS (2 * BUFSZ + HALOSZ + TSTEPS + 4)

__device__ __forceinline__ uint32_t s2u(const void* p) {
    return (uint32_t)__cvta_generic_to_shared((void*)p);
}
__device__ __forceinline__ uint32_t mapa_u32(uint32_t a, uint32_t r) {
    uint32_t d;
    asm("mapa.shared::cluster.u32 %0, %1, %2;" : "=r"(d) : "r"(a), "r"(r));
    return d;
}
__device__ __forceinline__ void st_cluster_f32(uint32_t a, float v) {
    asm volatile("st.shared::cluster.f32 [%0], %1;" :: "r"(a), "f"(v) : "memory");
}
__device__ __forceinline__ void cl_arrive() {
    asm volatile("barrier.cluster.arrive.aligned;" ::: "memory");
}
__device__ __forceinline__ void cl_wait() {
    asm volatile("barrier.cluster.wait.aligned;" ::: "memory");
}

__device__ __forceinline__ float pml1(int i) {
    int d;
    if (i <= 20)           d = 20 - i;
    else if (i >= NG - 21) d = i - (NG - 21);
    else return 0.0f;
    double t = (double)d * 0.05;
    double t2 = t * t;
    return (float)(3.0 * t2 * t2);
}

__global__ void __cluster_dims__(CS, 1, 1) __launch_bounds__(NTHR, 1)
wave_kernel(const float* __restrict__ x, const float* __restrict__ rho,
            float* __restrict__ out)
{
    extern __shared__ float dsm[];
    float* buf0 = dsm;                    // even-time states, rows -1..24
    float* buf1 = dsm + BUFSZ;            // odd-time states
    float* halo = dsm + 2 * BUFSZ;        // [p][side][idx][NGP]
    float* xs   = halo + HALOSZ;
    float* pbuf = xs + TSTEPS;

    const int tid   = threadIdx.x;
    const int col   = tid % NG;
    const int rgrp  = tid / NG;           // 0..3, rows 6*rgrp..6*rgrp+5
    const int rank  = blockIdx.x % CS;
    const int batch = blockIdx.x / CS;

    for (int i = tid; i < 2 * BUFSZ + HALOSZ; i += NTHR) dsm[i] = 0.f;
    for (int i = tid; i < TSTEPS; i += NTHR) xs[i] = x[batch * TSTEPS + i];

    // ---- coefficients: yn = Qp*c - Qm*y2 + Rc*(n+s+w+e) ----
    const float HM2 = (float)(1.0 / (2.01 * 2.01));
    auto coef = [&](int g, float& oQp, float& oQm, float& oRc) {
        float cc = rho[g * NG + col];
        float nn = (g > 0)      ? rho[(g - 1) * NG + col] : 0.f;
        float ss = (g < NG - 1) ? rho[(g + 1) * NG + col] : 0.f;
        float ww = (col > 0)    ? rho[g * NG + col - 1]   : 0.f;
        float ee = (col < NG-1) ? rho[g * NG + col + 1]   : 0.f;
        float lpf = 0.5f * cc + 0.125f * (nn + ss + ww + ee);
        float pr  = (1.0f + tanhf(100.0f * (lpf - 0.5f))) * 0.5f;
        float c   = 1.0f - 0.1f * pr;
        float bx = pml1(g), by = pml1(col);
        float bb = sqrtf(bx * bx + by * by);
        float A1 = 1.0f / (1.0f + 0.5f * bb);
        float Q  = A1 * (1.0f - 0.5f * bb);
        float R  = A1 * (c * c) * HM2;
        oQp = 1.0f + Q - 4.0f * R; oQm = Q; oRc = R;
    };
    float Qp[6], Qm[6], Rc[6], y2[6];
#pragma unroll
    for (int k = 0; k < 6; ++k) {
        coef(rank * 24 + rgrp * 6 + k, Qp[k], Qm[k], Rc[k]);
        y2[k] = 0.f;
    }
    const bool doUp = (rgrp == 0) && (rank > 0);
    const bool doDn = (rgrp == 3) && (rank < CS - 1);
    float eQp = 0.f, eQm = 0.f, eRc = 0.f;
    if (doUp) coef(rank * 24 - 1, eQp, eQm, eRc);
    if (doDn) coef(rank * 24 + 24, eQp, eQm, eRc);

    // halo read pointers (boundary rgrps; side 0=top for rgrp0, 1=bot for rgrp3)
    const int side = (rgrp == 3) ? 1 : 0;
    const float* h0[2]; const float* h1[2]; const float* h2[2];
#pragma unroll
    for (int p = 0; p < 2; ++p) {
        h0[p] = halo + ((p * 2 + side) * 3 + 0) * NGP + col + 1;   // y(t) row ∓2
        h1[p] = halo + ((p * 2 + side) * 3 + 1) * NGP + col + 1;   // y(t) row ∓1
        h2[p] = halo + ((p * 2 + side) * 3 + 2) * NGP + col + 1;   // y(t-1) row ∓1
    }
    // push addresses into neighbor's opposite-side halo
    uint32_t pa0[2] = {0,0}, pa1[2] = {0,0}, pa2[2] = {0,0};
    if (doUp | doDn) {
        int nr = doUp ? rank - 1 : rank + 1;
        int ts = doUp ? 1 : 0;
#pragma unroll
        for (int p = 0; p < 2; ++p) {
            pa0[p] = mapa_u32(s2u(halo + ((p * 2 + ts) * 3 + 0) * NGP + col + 1), (uint32_t)nr);
            pa1[p] = mapa_u32(s2u(halo + ((p * 2 + ts) * 3 + 1) * NGP + col + 1), (uint32_t)nr);
            pa2[p] = mapa_u32(s2u(halo + ((p * 2 + ts) * 3 + 2) * NGP + col + 1), (uint32_t)nr);
        }
    }

    // cell pointers (buffer row = 1 + rgrp*6 .. field row rgrp*6)
    const float* q0 = buf0 + (1 + rgrp * 6) * PITCH + col + 2;
    float*       q1 = buf1 + (1 + rgrp * 6) * PITCH + col + 2;
    float*       q0w = const_cast<float*>(q0);

    // Source (40,96): rank1 rgrp2 k4. Probes (160,{48,96,144}): rank6 rgrp2 k4.
    const bool isSrc = (rank == 1) && (rgrp == 2) && (col == 96);
    const bool isPrb = (rank == 6) && (rgrp == 2) &&
                       ((col == 48) | (col == 96) | (col == 144));
    float pacc = 0.f, pub = 0.f;

    cl_arrive(); cl_wait();   // init visible cluster-wide

    for (int b = 0; b < NBLK; ++b) {
        const int hp = b & 1, hq = hp ^ 1;
        const float xs1 = xs[2 * b];
        const float xs2 = xs[2 * b + 1];

        // ================= step 1: t -> t+1 (read buf0, write buf1) =========
        if (rgrp == 0) {
            float hc = h1[hp][0], hn = h0[hp][0];
            float hw = h1[hp][-1], he = h1[hp][1], hy = h2[hp][0];
            float s0 = q0[0];
            q1[-PITCH] = fmaf(eQp, hc, fmaf(-eQm, hy, eRc * ((hn + s0) + (hw + he))));
            float n = hc, c = s0;
#pragma unroll
            for (int k = 0; k < 6; ++k) {
                float s = q0[(k + 1) * PITCH];
                float w = q0[k * PITCH - 1], e = q0[k * PITCH + 1];
                float yn = fmaf(Qp[k], c, fmaf(-Qm[k], y2[k], Rc[k] * ((n + s) + (w + e))));
                q1[k * PITCH] = yn;
                if (k == 0) pub = yn;
                y2[k] = c; n = c; c = s;
            }
        } else if (rgrp == 3) {
            float hc = h1[hp][0];
            float n = q0[-PITCH], c = q0[0];
#pragma unroll
            for (int k = 0; k < 6; ++k) {
                float s = (k == 5) ? hc : q0[(k + 1) * PITCH];
                float w = q0[k * PITCH - 1], e = q0[k * PITCH + 1];
                float yn = fmaf(Qp[k], c, fmaf(-Qm[k], y2[k], Rc[k] * ((n + s) + (w + e))));
                q1[k * PITCH] = yn;
                if (k == 5) pub = yn;
                y2[k] = c; n = c; c = s;
            }
            float hn = y2[5], hs = h0[hp][0];
            float hw = h1[hp][-1], he = h1[hp][1], hy = h2[hp][0];
            q1[6 * PITCH] = fmaf(eQp, hc, fmaf(-eQm, hy, eRc * ((hn + hs) + (hw + he))));
        } else {
            float n = q0[-PITCH], c = q0[0];
#pragma unroll
            for (int k = 0; k < 6; ++k) {
                float s = q0[(k + 1) * PITCH];
                float w = q0[k * PITCH - 1], e = q0[k * PITCH + 1];
                float yn = fmaf(Qp[k], c, fmaf(-Qm[k], y2[k], Rc[k] * ((n + s) + (w + e))));
                if (k == 4) {
                    if (isSrc) yn += xs1;
                    if (isPrb) pacc = fmaf(yn, yn, pacc);
                }
                q1[k * PITCH] = yn;
                y2[k] = c; n = c; c = s;
            }
        }
        __syncthreads();   // y(t+1) incl. ext rows visible intra-CTA

        // ================= step 2: t+1 -> t+2 (read buf1, write buf0) =======
        auto s2 = [&](int k) -> float {
            float c = q1[k * PITCH];
            float n = q1[(k - 1) * PITCH], s = q1[(k + 1) * PITCH];
            float w = q1[k * PITCH - 1], e = q1[k * PITCH + 1];
            float yn = fmaf(Qp[k], c, fmaf(-Qm[k], y2[k], Rc[k] * ((n + s) + (w + e))));
            q0w[k * PITCH] = yn;
            y2[k] = c;
            return yn;
        };

        if (rgrp == 0) {
            float b0 = s2(0), b1 = s2(1);
            if (doUp) {
                st_cluster_f32(pa1[hq], b0);   // y(t+2) row 0 -> nbr y(t) row 24
                st_cluster_f32(pa0[hq], b1);   // y(t+2) row 1 -> nbr y(t) row 25
                st_cluster_f32(pa2[hq], pub);  // y(t+1) row 0 -> nbr y(t-1) row 24
            }
        } else if (rgrp == 3) {
            float b0 = s2(5), b1 = s2(4);
            if (doDn) {
                st_cluster_f32(pa1[hq], b0);   // y(t+2) row 23 -> nbr y(t) row -1
                st_cluster_f32(pa0[hq], b1);   // y(t+2) row 22 -> nbr y(t) row -2
                st_cluster_f32(pa2[hq], pub);  // y(t+1) row 23 -> nbr y(t-1) row -1
            }
        }
        cl_arrive();   // release pushes; interior compute overlaps barrier

        if (rgrp == 0) {
            s2(2); s2(3); s2(4); s2(5);
        } else if (rgrp == 3) {
            s2(3); s2(2); s2(1); s2(0);
        } else {
#pragma unroll
            for (int k = 0; k < 6; ++k) {
                float yn = s2(k);
                if (k == 4) {
                    if (isSrc) { yn += xs2; q0w[4 * PITCH] = yn; }
                    if (isPrb) pacc = fmaf(yn, yn, pacc);
                }
            }
        }
        __syncthreads();   // y(t+2) visible intra-CTA before next block reads
        cl_wait();         // neighbors' halo pushes for next block visible
    }

    if (isPrb) pbuf[(col - 48) / 48] = pacc;
    __syncthreads();
    if (rank == 6 && tid == 0) {
        float a = pbuf[0], b = pbuf[1], c = pbuf[2];
        float s = a + b + c;
        out[batch * 3 + 0] = a / s;
        out[batch * 3 + 1] = b / s;
        out[batch * 3 + 2] = c / s;
    }
}

extern "C" void kernel_launch(void* const* d_in, const int* in_sizes, int n_in,
                              void* d_out, int out_size)
{
    (void)in_sizes; (void)n_in; (void)out_size;
    const float* x   = (const float*)d_in[0];   // (4,256) f32
    const float* rho = (const float*)d_in[1];   // (192,192) f32
    float* out = (float*)d_out;                 // (4,3) f32
    static int configured = 0;
    if (!configured) {
        cudaFuncSetAttribute(wave_kernel,
                             cudaFuncAttributeMaxDynamicSharedMemorySize,
                             SMEMFLOATS * (int)sizeof(float));
        configured = 1;
    }
    wave_kernel<<<dim3(CS * 4), dim3(NTHR), SMEMFLOATS * sizeof(float)>>>(x, rho, out);
}